// round 7
// baseline (speedup 1.0000x reference)
#include <cuda_runtime.h>
#include <cuda_bf16.h>
#include <cstdint>
#include <cstddef>

// Problem dims
#define BB   128
#define TT   512
#define EE   256
#define UU   512
#define ZZ   2048          // 4*U
#define NCU  64            // u-groups (8 units each)
#define UT   8             // units per CTA group
#define CPC  32            // z-cols per CTA (4 gates * 8 units)
#define NCTA 128           // persistent grid

typedef __nv_bfloat16 bf16;

// ---------------- scratch (device globals; no allocations) ----------------
__device__ __align__(16) bf16  g_emb16[32000 * EE];          // bf16 embedding (16.4 MB)
__device__ __align__(16) bf16  g_WxGt [ZZ * EE];             // gathered Wx, [gc][k] (1 MB)
__device__ __align__(16) bf16  g_WhGt [NCU * CPC * UU];      // gathered Wh, [cu][jp][k] (2 MB)
__device__ __align__(16) float g_bG   [ZZ];                  // gathered bias
__device__ __align__(16) float g_zx   [(size_t)BB * TT * ZZ];// x@Wx + b, [t][b][gathered 2048] (512 MB)
__device__ __align__(16) bf16  g_hbuf [2 * BB * UU];         // double-buffered hidden state (bf16)
__device__ __align__(16) unsigned g_flags[NCTA * 32];        // per-CTA epoch flags, 128B padded

// gather map: gc -> original column
__device__ __forceinline__ int orig_col(int gc) {
    int cu   = gc >> 5;
    int gate = (gc >> 3) & 3;
    int j    = gc & 7;
    return gate * UU + cu * UT + j;
}

__device__ __forceinline__ float tanh_apx(float x) {
    float y;
    asm("tanh.approx.f32 %0, %1;" : "=f"(y) : "f"(x));
    return y;
}
__device__ __forceinline__ float sigm_apx(float x) {
    return fmaf(tanh_apx(0.5f * x), 0.5f, 0.5f);
}

__device__ __forceinline__ void mma_bf16(float& d0, float& d1, float& d2, float& d3,
                                         uint32_t a0, uint32_t a1, uint32_t a2, uint32_t a3,
                                         uint32_t b0, uint32_t b1) {
    asm volatile(
        "mma.sync.aligned.m16n8k16.row.col.f32.bf16.bf16.f32 "
        "{%0,%1,%2,%3}, {%4,%5,%6,%7}, {%8,%9}, {%0,%1,%2,%3};"
        : "+f"(d0), "+f"(d1), "+f"(d2), "+f"(d3)
        : "r"(a0), "r"(a1), "r"(a2), "r"(a3), "r"(b0), "r"(b1));
}

__device__ __forceinline__ void ldsm_x4(uint32_t& r0, uint32_t& r1, uint32_t& r2, uint32_t& r3,
                                        uint32_t addr) {
    asm volatile("ldmatrix.sync.aligned.m8n8.x4.shared.b16 {%0,%1,%2,%3}, [%4];"
                 : "=r"(r0), "=r"(r1), "=r"(r2), "=r"(r3) : "r"(addr));
}

__device__ __forceinline__ uint32_t ldpair(const bf16* p) {
    return *(const uint32_t*)p;
}

__device__ __forceinline__ void cp_async16(uint32_t dst_smem, const void* src) {
    asm volatile("cp.async.cg.shared.global [%0], [%1], 16;" :: "r"(dst_smem), "l"(src));
}

// ---------------- init kernels ----------------
__global__ void k_cvt_emb(const float* __restrict__ src) {
    int n4 = 32000 * EE / 4;
    for (int i = blockIdx.x * blockDim.x + threadIdx.x; i < n4; i += gridDim.x * blockDim.x) {
        float4 v = *(const float4*)(src + (size_t)i * 4);
        bf16* d = g_emb16 + (size_t)i * 4;
        d[0] = __float2bfloat16(v.x);
        d[1] = __float2bfloat16(v.y);
        d[2] = __float2bfloat16(v.z);
        d[3] = __float2bfloat16(v.w);
    }
}

__global__ void k_gather_wx(const float* __restrict__ Wx, const float* __restrict__ bvec) {
    int n = ZZ * EE;
    for (int i = blockIdx.x * blockDim.x + threadIdx.x; i < n; i += gridDim.x * blockDim.x) {
        int gc = i >> 8;          // / 256
        int k  = i & 255;
        g_WxGt[i] = __float2bfloat16(Wx[(size_t)k * ZZ + orig_col(gc)]);
    }
    int t = blockIdx.x * blockDim.x + threadIdx.x;
    if (t < ZZ) g_bG[t] = bvec[orig_col(t)];
}

__global__ void k_gather_wh(const float* __restrict__ Wh) {
    int n = NCU * CPC * UU;
    for (int i = blockIdx.x * blockDim.x + threadIdx.x; i < n; i += gridDim.x * blockDim.x) {
        int cu = i >> 14;             // / (32*512)
        int jp = (i >> 9) & 31;
        int k  = i & 511;
        int gate = jp >> 3;
        int j    = jp & 7;
        g_WhGt[i] = __float2bfloat16(Wh[(size_t)k * ZZ + gate * UU + cu * UT + j]);
    }
}

__global__ void k_zero_state() {
    int tid = blockIdx.x * blockDim.x + threadIdx.x;
    int n = BB * UU;
    for (int i = tid; i < n; i += gridDim.x * blockDim.x)
        g_hbuf[i] = __float2bfloat16(0.0f);
    for (int i = tid; i < NCTA * 32; i += gridDim.x * blockDim.x)
        g_flags[i] = 0u;
}

// ---------------- phase 1: z_x = emb[sentence] @ Wx + b (gathered cols) ----------------
__global__ __launch_bounds__(256) void k_phase1(const int* __restrict__ sentence) {
    extern __shared__ __align__(16) char dsm[];
    bf16* Bs   = (bf16*)dsm;                       // stride 264
    bf16* As   = (bf16*)(dsm + 33792);             // stride 72
    int*  toks = (int*) (dsm + 33792 + 18432);

    int tid  = threadIdx.x;
    int warp = tid >> 5;
    int lane = tid & 31;
    int tg   = lane & 3;
    int gid  = lane >> 2;

    int n0    = (blockIdx.x & 31) * 64;
    int tbase = (blockIdx.x >> 5) * 16;

    int wm = (warp >> 1) * 32;
    int wn = (warp & 1) * 32;

#pragma unroll
    for (int r = 0; r < 8; r++) {
        int i   = tid + 256 * r;
        int row = i >> 5;
        int seg = i & 31;
        *(uint4*)(Bs + row * 264 + seg * 8) =
            *(const uint4*)(g_WxGt + (size_t)(n0 + row) * EE + seg * 8);
    }

    float bi[4][2];
#pragma unroll
    for (int nt = 0; nt < 4; nt++) {
        int col = n0 + wn + nt * 8 + tg * 2;
        bi[nt][0] = g_bG[col];
        bi[nt][1] = g_bG[col + 1];
    }
    __syncthreads();

    for (int tt = 0; tt < 16; tt++) {
        int t = tbase + tt;
        if (tid < 128) toks[tid] = sentence[tid * TT + t];
        __syncthreads();

        float acc[2][4][4];
#pragma unroll
        for (int mt = 0; mt < 2; mt++)
#pragma unroll
            for (int nt = 0; nt < 4; nt++)
#pragma unroll
                for (int q = 0; q < 4; q++) acc[mt][nt][q] = 0.0f;

        for (int kc = 0; kc < EE; kc += 64) {
#pragma unroll
            for (int r = 0; r < 4; r++) {
                int i   = tid + 256 * r;
                int row = i >> 3;
                int seg = i & 7;
                *(uint4*)(As + row * 72 + seg * 8) =
                    *(const uint4*)(g_emb16 + (size_t)toks[row] * EE + kc + seg * 8);
            }
            __syncthreads();

#pragma unroll
            for (int k16 = 0; k16 < 4; k16++) {
                int kbA = k16 * 16;
                int kbB = kc + k16 * 16;
                uint32_t a[2][4];
#pragma unroll
                for (int mt = 0; mt < 2; mt++) {
                    const bf16* p = As + (wm + mt * 16 + gid) * 72 + kbA + tg * 2;
                    a[mt][0] = ldpair(p);
                    a[mt][1] = ldpair(p + 8 * 72);
                    a[mt][2] = ldpair(p + 8);
                    a[mt][3] = ldpair(p + 8 * 72 + 8);
                }
                uint32_t bfr[4][2];
#pragma unroll
                for (int nt = 0; nt < 4; nt++) {
                    const bf16* p = Bs + (wn + nt * 8 + gid) * 264 + kbB + tg * 2;
                    bfr[nt][0] = ldpair(p);
                    bfr[nt][1] = ldpair(p + 8);
                }
#pragma unroll
                for (int mt = 0; mt < 2; mt++)
#pragma unroll
                    for (int nt = 0; nt < 4; nt++)
                        mma_bf16(acc[mt][nt][0], acc[mt][nt][1], acc[mt][nt][2], acc[mt][nt][3],
                                 a[mt][0], a[mt][1], a[mt][2], a[mt][3],
                                 bfr[nt][0], bfr[nt][1]);
            }
            __syncthreads();
        }

#pragma unroll
        for (int mt = 0; mt < 2; mt++) {
#pragma unroll
            for (int nt = 0; nt < 4; nt++) {
                int b   = wm + mt * 16 + gid;
                int col = n0 + wn + nt * 8 + tg * 2;
                size_t r0 = ((size_t)t * BB + b) * ZZ + col;
                size_t r2 = ((size_t)t * BB + b + 8) * ZZ + col;
                float2 v0 = { acc[mt][nt][0] + bi[nt][0], acc[mt][nt][1] + bi[nt][1] };
                float2 v2 = { acc[mt][nt][2] + bi[nt][0], acc[mt][nt][3] + bi[nt][1] };
                *(float2*)(g_zx + r0) = v0;
                *(float2*)(g_zx + r2) = v2;
            }
        }
    }
}

// ---------------- phase 2: persistent recurrence ----------------
// 128 CTAs x 512 threads (16 warps). cu = bx&63, mg = bx>>6.
// Warp (mw = warp&3, kw = warp>>2): m-tile mw*16, K-slice kw*128.
// kw!=0 partials reduced via smem; kw==0 warps do gate math (c in regs).
// dyn smem: Bs (Wh) 32x520 bf16 (33280) | hs 64x520 bf16 (66560) | sred 16*12*32 f32 (24576)
__global__ __launch_bounds__(512) void k_recur() {
    extern __shared__ __align__(16) char dsm[];
    bf16*  Bs   = (bf16*)dsm;                        // Wh slice, stride 520
    bf16*  hs   = (bf16*)(dsm + 33280);              // h tile, stride 520
    float* sred = (float*)(dsm + 33280 + 66560);     // partial-z reduction

    uint32_t Bs_u32 = (uint32_t)__cvta_generic_to_shared(Bs);
    uint32_t hs_u32 = (uint32_t)__cvta_generic_to_shared(hs);

    int tid  = threadIdx.x;
    int warp = tid >> 5;
    int lane = tid & 31;
    int tg   = lane & 3;
    int gid  = lane >> 2;

    int mw = warp & 3;
    int kw = warp >> 2;

    int cu = blockIdx.x & 63;
    int mg = blockIdx.x >> 6;
    int m0 = mg * 64;
    int wm = mw * 16;

    // preload Wh slice (32 x 512 bf16)
    {
        const bf16* Wp = g_WhGt + (size_t)cu * CPC * UU;
        for (int i = tid; i < 2048; i += 512) {
            int n   = i >> 6;
            int seg = i & 63;
            *(uint4*)(Bs + n * 520 + seg * 8) = *(const uint4*)(Wp + n * UU + seg * 8);
        }
    }

    // ldmatrix lane addresses (byte offsets), invariant across steps; kw slice = +kw*256 bytes
    uint32_t aAddr  = hs_u32 + (uint32_t)((wm + (lane & 15)) * 520 * 2 + kw * 256 + ((lane & 16) ? 16 : 0));
    uint32_t bAddr0 = Bs_u32 + (uint32_t)(((0  + (lane & 7) + ((lane & 16) ? 8 : 0)) * 520) * 2 + kw * 256 + ((lane & 8) ? 16 : 0));
    uint32_t bAddr1 = Bs_u32 + (uint32_t)(((16 + (lane & 7) + ((lane & 16) ? 8 : 0)) * 520) * 2 + kw * 256 + ((lane & 8) ? 16 : 0));

    // gate-warp (kw==0) ownership: rows (m0+wm+gid, +8), units (cu*8 + tg*2, +1)
    int rowA = m0 + wm + gid;
    float c00 = 0.0f, c01 = 0.0f, c10 = 0.0f, c11 = 0.0f;

    unsigned* myflag   = g_flags + (size_t)(mg * 64 + cu) * 32;
    unsigned* pollflag = g_flags + (size_t)(mg * 64 + (tid & 63)) * 32;

    for (int t = 0; t < TT; t++) {
        int p = t & 1;
        const bf16* hsrc = g_hbuf + p * (BB * UU);
        bf16*       hdst = g_hbuf + (p ^ 1) * (BB * UU);

        // z_x prefetch (only consumed by kw==0 warps)
        float2 zi0, zf0, zg0, zo0, zi1, zf1, zg1, zo1;
        if (kw == 0) {
            const float* zxr0 = g_zx + ((size_t)t * BB + rowA) * ZZ + cu * CPC + tg * 2;
            const float* zxr1 = zxr0 + 8 * ZZ;
            zi0 = *(const float2*)(zxr0);
            zf0 = *(const float2*)(zxr0 + 8);
            zg0 = *(const float2*)(zxr0 + 16);
            zo0 = *(const float2*)(zxr0 + 24);
            zi1 = *(const float2*)(zxr1);
            zf1 = *(const float2*)(zxr1 + 8);
            zg1 = *(const float2*)(zxr1 + 16);
            zo1 = *(const float2*)(zxr1 + 24);
        }

        // stage h tile 64x512 bf16 = 4096 uint4: row = i>>6 (0..63), seg = i&63 (0..63)
#pragma unroll
        for (int r = 0; r < 8; r++) {
            int i   = r * 512 + tid;     // 0..4095
            int row = i >> 6;
            int seg = i & 63;
            cp_async16(hs_u32 + (uint32_t)((row * 520 + seg * 8) * 2),
                       hsrc + (size_t)(m0 + row) * UU + seg * 8);
        }
        asm volatile("cp.async.commit_group;\ncp.async.wait_group 0;" ::: "memory");
        __syncthreads();

        float acc[4][4];   // [gate][q]
#pragma unroll
        for (int g = 0; g < 4; g++)
#pragma unroll
            for (int q = 0; q < 4; q++) acc[g][q] = 0.0f;

#pragma unroll
        for (int ks = 0; ks < 8; ks++) {
            uint32_t kb = (uint32_t)(ks * 32);
            uint32_t a0, a1, a2, a3, b0, b1, b2, b3, b4, b5, b6, b7;
            ldsm_x4(a0, a1, a2, a3, aAddr + kb);
            ldsm_x4(b0, b1, b2, b3, bAddr0 + kb);
            ldsm_x4(b4, b5, b6, b7, bAddr1 + kb);
            mma_bf16(acc[0][0], acc[0][1], acc[0][2], acc[0][3], a0, a1, a2, a3, b0, b1);
            mma_bf16(acc[1][0], acc[1][1], acc[1][2], acc[1][3], a0, a1, a2, a3, b2, b3);
            mma_bf16(acc[2][0], acc[2][1], acc[2][2], acc[2][3], a0, a1, a2, a3, b4, b5);
            mma_bf16(acc[3][0], acc[3][1], acc[3][2], acc[3][3], a0, a1, a2, a3, b6, b7);
        }

        // K-split reduction: kw!=0 store partials
        if (kw != 0) {
#pragma unroll
            for (int g = 0; g < 4; g++)
#pragma unroll
                for (int q = 0; q < 4; q++)
                    sred[((g * 4 + q) * 12 + (kw - 1) * 4 + mw) * 32 + lane] = acc[g][q];
        }
        __syncthreads();

        if (kw == 0) {
#pragma unroll
            for (int g = 0; g < 4; g++)
#pragma unroll
                for (int q = 0; q < 4; q++) {
#pragma unroll
                    for (int j = 0; j < 3; j++)
                        acc[g][q] += sred[((g * 4 + q) * 12 + j * 4 + mw) * 32 + lane];
                }

            // gate update fully in registers
            float i0 = sigm_apx(zi0.x + acc[0][0]), f0 = sigm_apx(zf0.x + acc[1][0]);
            float gg0 = tanh_apx(zg0.x + acc[2][0]), o0 = sigm_apx(zo0.x + acc[3][0]);
            c00 = f0 * c00 + i0 * gg0;
            float h00 = o0 * tanh_apx(c00);

            float i1 = sigm_apx(zi0.y + acc[0][1]), f1 = sigm_apx(zf0.y + acc[1][1]);
            float gg1 = tanh_apx(zg0.y + acc[2][1]), o1 = sigm_apx(zo0.y + acc[3][1]);
            c01 = f1 * c01 + i1 * gg1;
            float h01 = o1 * tanh_apx(c01);

            float i2 = sigm_apx(zi1.x + acc[0][2]), f2 = sigm_apx(zf1.x + acc[1][2]);
            float gg2 = tanh_apx(zg1.x + acc[2][2]), o2 = sigm_apx(zo1.x + acc[3][2]);
            c10 = f2 * c10 + i2 * gg2;
            float h10 = o2 * tanh_apx(c10);

            float i3 = sigm_apx(zi1.y + acc[0][3]), f3 = sigm_apx(zf1.y + acc[1][3]);
            float gg3 = tanh_apx(zg1.y + acc[2][3]), o3 = sigm_apx(zo1.y + acc[3][3]);
            c11 = f3 * c11 + i3 * gg3;
            float h11 = o3 * tanh_apx(c11);

            __nv_bfloat162 hA, hB;
            hA.x = __float2bfloat16(h00); hA.y = __float2bfloat16(h01);
            hB.x = __float2bfloat16(h10); hB.y = __float2bfloat16(h11);
            size_t base = (size_t)rowA * UU + cu * UT + tg * 2;
            *(__nv_bfloat162*)(hdst + base)          = hA;
            *(__nv_bfloat162*)(hdst + base + 8 * UU) = hB;
        }

        // group barrier: flag-array, contention-free
        __syncthreads();
        if (tid == 0) {
            asm volatile("st.release.gpu.u32 [%0], %1;" :: "l"(myflag), "r"(t + 1) : "memory");
        }
        if (tid < 64) {
            unsigned v;
            do {
                asm volatile("ld.acquire.gpu.u32 %0, [%1];" : "=r"(v) : "l"(pollflag));
            } while (v < (unsigned)(t + 1));
        }
        __syncthreads();
    }
}

// ---------------- head: per-batch MLP ----------------
__global__ __launch_bounds__(128) void k_head(const float* __restrict__ W1, const float* __restrict__ b1,
                                              const float* __restrict__ W2, const float* __restrict__ b2,
                                              const float* __restrict__ W3, const float* __restrict__ b3,
                                              float* __restrict__ out) {
    __shared__ float hs[UU];
    __shared__ float h1[128];
    __shared__ float red[64];
    int b   = blockIdx.x;
    int tid = threadIdx.x;

    for (int i = tid; i < UU; i += 128) hs[i] = __bfloat162float(g_hbuf[b * UU + i]);
    __syncthreads();

    float a1 = b1[tid];
#pragma unroll 8
    for (int k = 0; k < UU; k++) a1 += hs[k] * W1[k * 128 + tid];
    h1[tid] = fmaxf(a1, 0.0f);
    __syncthreads();

    if (tid < 64) {
        float a2 = b2[tid];
#pragma unroll 8
        for (int k = 0; k < 128; k++) a2 += h1[k] * W2[k * 64 + tid];
        a2 = fmaxf(a2, 0.0f);
        red[tid] = a2 * W3[tid];
    }
    __syncthreads();

    if (tid == 0) {
        float s = b3[0];
#pragma unroll 8
        for (int k = 0; k < 64; k++) s += red[k];
        out[b] = 1.0f / (1.0f + expf(-s));
    }
}

// ---------------- launch ----------------
extern "C" void kernel_launch(void* const* d_in, const int* in_sizes, int n_in,
                              void* d_out, int out_size) {
    const int*   sentence = (const int*)  d_in[0];
    const float* emb      = (const float*)d_in[1];
    const float* Wx       = (const float*)d_in[2];
    const float* Wh       = (const float*)d_in[3];
    const float* bvec     = (const float*)d_in[4];
    const float* W1       = (const float*)d_in[5];
    const float* b1       = (const float*)d_in[6];
    const float* W2       = (const float*)d_in[7];
    const float* b2       = (const float*)d_in[8];
    const float* W3       = (const float*)d_in[9];
    const float* b3       = (const float*)d_in[10];
    float* out = (float*)d_out;

    static bool attr_done = false;
    if (!attr_done) {
        cudaFuncSetAttribute(k_phase1, cudaFuncAttributeMaxDynamicSharedMemorySize, 52736);
        cudaFuncSetAttribute(k_recur,  cudaFuncAttributeMaxDynamicSharedMemorySize, 124416);
        attr_done = true;
    }

    k_cvt_emb<<<4096, 256>>>(emb);
    k_gather_wx<<<2048, 256>>>(Wx, bvec);
    k_gather_wh<<<4096, 256>>>(Wh);
    k_zero_state<<<256, 256>>>();

    k_phase1<<<1024, 256, 52736>>>(sentence);

    k_recur<<<NCTA, 512, 124416>>>();

    k_head<<<128, 128>>>(W1, b1, W2, b2, W3, b3, out);
}